// round 15
// baseline (speedup 1.0000x reference)
#include <cuda_runtime.h>

// GCBFSafetyLayer — FINAL (terminal at the graph-replay floor).
//
// Math: the reference QP projection passes A = L_g_h = jnp.zeros(...) into
// the per-constraint solver; every update is gated by (nrm > 1e-6) with
// nrm = sum(a_j^2) = 0, so the gate is always false and scan/fori_loop
// return u0 unchanged. safe_action == raw_action bit-exactly (rel_err = 0.0
// on all 14 benched rounds). Work reduces to one 32 KB D2D move of
// d_in[3] -> d_out (~8ns of HBM time at 8TB/s = 0.2% of measured total).
//
// Evidence of floor (15 runs): champion binary (16x128 kernel node) samples
// 4.576/4.608/5.856/4.832/4.608/4.864/5.888/4.864/4.608us (n=9, min 4.576,
// median 4.832, mode 4.608); driver memcpy node ties the min at 4.575999us
// exactly; 8x256 at 4.61us. Kernel-internal time (3.55-4.38us, issue<1%,
// DRAM 0.1%, regs=16) is uncorrelated with totals (R8: best internal
// 3.68us inside a 5.86us total) -> variance is harness-side replay
// scheduling. Swept and exhausted: node mechanism, grid {1,8,16,32},
// block {64,128,256}, branchy/branchless, unroll, constant blockDim.
// Genuine cliffs only at grid=1 (single-SM L1tex queue serialization) and
// 32x64 (latency-exposed 2-warp blocks) — both avoided. No hypothesis
// predicts a delta above the ±0.7us noise band; edits would be noise-mining.

__global__ void __launch_bounds__(128, 1)
copy_exact_kernel(const float4* __restrict__ src, float4* __restrict__ dst) {
    // blockDim compile-time constant (128): body is IMAD + LDG.128 +
    // STG.128 + EXIT.
    int i = blockIdx.x * 128 + threadIdx.x;
    dst[i] = src[i];
}

// Generic fallback for unexpected sizes.
__global__ void copy_generic_kernel(const float* __restrict__ src,
                                    float* __restrict__ dst, int n) {
    int i = blockIdx.x * blockDim.x + threadIdx.x;
    if (i < n) dst[i] = src[i];
}

extern "C" void kernel_launch(void* const* d_in, const int* in_sizes, int n_in,
                              void* d_out, int out_size) {
    const float* raw_action = (const float*)d_in[3];
    float* out = (float*)d_out;

    if ((out_size & 511) == 0) {
        // Multiple of 512 floats: grid = out_size/512 blocks of 128 threads,
        // one float4 per thread. For 8192 floats -> grid=16 (measured best).
        int blocks = out_size / 512;
        copy_exact_kernel<<<blocks, 128>>>((const float4*)raw_action,
                                           (float4*)out);
    } else {
        int threads = 256;
        int blocks = (out_size + threads - 1) / threads;
        copy_generic_kernel<<<blocks, threads>>>(raw_action, out, out_size);
    }
}